// round 4
// baseline (speedup 1.0000x reference)
#include <cuda_runtime.h>
#include <math.h>

#define NN 50000
#define EE 400000
#define HD 256
#define EPS 1e-5f

// ---------------- scratch (device globals, referenced BY NAME in device code) ----------------
__device__ __align__(16) float g_dinv[NN];                  // deg -> rsqrt(deg)
__device__ __align__(16) float g_buf1[(size_t)NN * HD];     // xw1 / h1 / agg2 / h2
__device__ __align__(16) float g_buf2[(size_t)NN * HD];     // agg1 / t (=h1@W2)
__device__ __align__(16) float g_AB[(size_t)NN * 512];      // [A | B] per node for edge MLP
__device__ __align__(16) float g_stats[512];                // per-channel sum, sumsq
__device__ __align__(16) float g_scale[HD];
__device__ __align__(16) float g_shift[HD];

__device__ __forceinline__ float* buf_sel(int s) {          // 1 -> buf1, 2 -> buf2, 3 -> AB
    return s == 1 ? g_buf1 : (s == 2 ? g_buf2 : g_AB);
}

// ---------------- small kernels ----------------
__global__ void k_init(int n) {
    int i = blockIdx.x * blockDim.x + threadIdx.x;
    if (i < n) g_dinv[i] = 1.0f;         // self loop contributes 1 to degree
    if (i < 512) g_stats[i] = 0.0f;
}

__global__ void k_deg_edges(const int* __restrict__ dst, int e) {
    int i = blockIdx.x * blockDim.x + threadIdx.x;
    if (i < e) atomicAdd(&g_dinv[dst[i]], 1.0f);
}

__global__ void k_dinv(int n) {
    int i = blockIdx.x * blockDim.x + threadIdx.x;
    if (i < n) g_dinv[i] = rsqrtf(g_dinv[i]);
}

// agg[i,:] = bias + xw[i,:] * dinv[i]^2   (self-loop term + bias init)
// flip=0: xw=buf1, agg=buf2 ; flip=1: xw=buf2, agg=buf1
__global__ void k_init_agg(const float* __restrict__ bias, int flip, int n) {
    int t = blockIdx.x * blockDim.x + threadIdx.x;          // over n*64 float4 units
    if (t >= n * 64) return;
    const float* xw = flip ? g_buf2 : g_buf1;
    float* agg      = flip ? g_buf1 : g_buf2;
    int node = t >> 6, q = (t & 63) << 2;
    float c = g_dinv[node]; c *= c;
    float4 v = *(const float4*)(xw + (size_t)node * HD + q);
    float4 b = *(const float4*)(bias + q);
    v.x = fmaf(v.x, c, b.x); v.y = fmaf(v.y, c, b.y);
    v.z = fmaf(v.z, c, b.z); v.w = fmaf(v.w, c, b.w);
    *(float4*)(agg + (size_t)node * HD + q) = v;
}

// per edge: agg[dst,:] += xw[src,:] * dinv[src]*dinv[dst]   (64 threads/edge, scalar RED.F32)
__global__ void k_edge_agg(const int* __restrict__ src, const int* __restrict__ dst,
                           int flip, int e) {
    int t = blockIdx.x * blockDim.x + threadIdx.x;
    int ei = t >> 6;
    if (ei >= e) return;
    const float* xw = flip ? g_buf2 : g_buf1;
    float* agg      = flip ? g_buf1 : g_buf2;
    int q = (t & 63) << 2;
    int s = src[ei], d = dst[ei];
    float c = g_dinv[s] * g_dinv[d];
    float4 v = *(const float4*)(xw + (size_t)s * HD + q);
    float* p = agg + (size_t)d * HD + q;
    atomicAdd(p + 0, v.x * c);
    atomicAdd(p + 1, v.y * c);
    atomicAdd(p + 2, v.z * c);
    atomicAdd(p + 3, v.w * c);
}

__global__ void k_bn_stats(int n) {                          // reads buf2
    int c = threadIdx.x;                                     // 256 channels
    float s = 0.f, s2 = 0.f;
    for (int r = blockIdx.x; r < n; r += gridDim.x) {
        float v = g_buf2[(size_t)r * HD + c];
        s += v; s2 += v * v;
    }
    atomicAdd(&g_stats[c], s);
    atomicAdd(&g_stats[HD + c], s2);
}

__global__ void k_bn_finalize(const float* __restrict__ gamma, const float* __restrict__ beta, int n) {
    int c = threadIdx.x;
    float inv_n = 1.0f / (float)n;
    float mu = g_stats[c] * inv_n;
    float var = g_stats[HD + c] * inv_n - mu * mu;
    float sc = gamma[c] * rsqrtf(var + EPS);
    g_scale[c] = sc;
    g_shift[c] = beta[c] - mu * sc;
}

// buf1[i] = relu(buf2[i]*scale[c] + shift[c])
__global__ void k_bn_apply(int n) {
    int t = blockIdx.x * blockDim.x + threadIdx.x;
    if (t >= n * 64) return;
    int node = t >> 6, q = (t & 63) << 2;
    float4 v = *(const float4*)(g_buf2 + (size_t)node * HD + q);
    float4 sc = *(const float4*)(g_scale + q);
    float4 sh = *(const float4*)(g_shift + q);
    v.x = fmaxf(fmaf(v.x, sc.x, sh.x), 0.f);
    v.y = fmaxf(fmaf(v.y, sc.y, sh.y), 0.f);
    v.z = fmaxf(fmaf(v.z, sc.z, sh.z), 0.f);
    v.w = fmaxf(fmaf(v.w, sc.w, sh.w), 0.f);
    *(float4*)(g_buf1 + (size_t)node * HD + q) = v;
}

__global__ void k_relu_buf1(size_t n4) {
    size_t t = (size_t)blockIdx.x * blockDim.x + threadIdx.x;
    if (t >= n4) return;
    float4 v = ((float4*)g_buf1)[t];
    v.x = fmaxf(v.x, 0.f); v.y = fmaxf(v.y, 0.f);
    v.z = fmaxf(v.z, 0.f); v.w = fmaxf(v.w, 0.f);
    ((float4*)g_buf1)[t] = v;
}

// ---------------- SGEMM: tiles 128x64x16. A: external (a_sel=0) or global buf; C: global buf ----------------
__global__ __launch_bounds__(256) void k_sgemm(const float* __restrict__ Aext, int a_sel,
                                               const float* __restrict__ B,
                                               int c_sel, int c_off,
                                               int M, int K, int ldb, int ldc) {
    const int BM = 128, BN = 64, BK = 16;
    __shared__ __align__(16) float As[BK][BM];
    __shared__ __align__(16) float Bs[BK][BN];
    const float* A = (a_sel == 0) ? Aext : buf_sel(a_sel);
    float* C = buf_sel(c_sel) + c_off;

    int tid = threadIdx.x;
    int m0 = blockIdx.y * BM;
    int n0 = blockIdx.x * BN;

    int a_r = tid >> 2;              // 0..63
    int a_c = (tid & 3) << 2;        // 0,4,8,12
    int b_r = tid >> 4;              // 0..15
    int b_c = (tid & 15) << 2;       // 0..60
    int ty = tid >> 4, tx = tid & 15;

    float acc[8][4];
#pragma unroll
    for (int i = 0; i < 8; i++)
#pragma unroll
        for (int j = 0; j < 4; j++) acc[i][j] = 0.f;

    for (int k0 = 0; k0 < K; k0 += BK) {
#pragma unroll
        for (int h = 0; h < 2; h++) {
            int r = m0 + a_r + h * 64;
            float4 v = make_float4(0.f, 0.f, 0.f, 0.f);
            if (r < M) v = *(const float4*)(A + (size_t)r * K + k0 + a_c);
            As[a_c + 0][a_r + h * 64] = v.x;
            As[a_c + 1][a_r + h * 64] = v.y;
            As[a_c + 2][a_r + h * 64] = v.z;
            As[a_c + 3][a_r + h * 64] = v.w;
        }
        *(float4*)&Bs[b_r][b_c] = *(const float4*)(B + (size_t)(k0 + b_r) * ldb + n0 + b_c);
        __syncthreads();
#pragma unroll
        for (int k = 0; k < BK; k++) {
            float a[8], b[4];
#pragma unroll
            for (int i = 0; i < 8; i++) a[i] = As[k][ty * 8 + i];
#pragma unroll
            for (int j = 0; j < 4; j++) b[j] = Bs[k][tx * 4 + j];
#pragma unroll
            for (int i = 0; i < 8; i++)
#pragma unroll
                for (int j = 0; j < 4; j++) acc[i][j] = fmaf(a[i], b[j], acc[i][j]);
        }
        __syncthreads();
    }
#pragma unroll
    for (int i = 0; i < 8; i++) {
        int r = m0 + ty * 8 + i;
        if (r < M) {
            float4 v = make_float4(acc[i][0], acc[i][1], acc[i][2], acc[i][3]);
            *(float4*)(C + (size_t)r * ldc + n0 + tx * 4) = v;
        }
    }
}

// ---------------- edge MLP: out[e] = sigmoid( relu(AB_A[s]+AB_B[d]+bm1) . Wm2 + bm2 ) ----------------
__global__ __launch_bounds__(256) void k_edge_mlp(const int* __restrict__ src,
                                                  const int* __restrict__ dst,
                                                  const float* __restrict__ bm1,
                                                  const float* __restrict__ Wm2,
                                                  const float* __restrict__ bm2,
                                                  float* __restrict__ out, int e) {
    __shared__ __align__(16) float w[HD];
    __shared__ __align__(16) float b[HD];
    int tid = threadIdx.x;
    w[tid] = Wm2[tid];
    b[tid] = bm1[tid];
    __syncthreads();
    int ei = blockIdx.x * 8 + (tid >> 5);
    if (ei >= e) return;
    int lane = tid & 31;
    int s = src[ei], d = dst[ei];
    const float* pa = g_AB + (size_t)s * 512;
    const float* pb = g_AB + (size_t)d * 512 + HD;
    float acc = 0.f;
#pragma unroll
    for (int it = 0; it < 2; it++) {
        int j = (it * 32 + lane) << 2;
        float4 va = *(const float4*)(pa + j);
        float4 vb = *(const float4*)(pb + j);
        float4 vbi = *(const float4*)(b + j);
        float4 vw = *(const float4*)(w + j);
        acc += fmaxf(va.x + vb.x + vbi.x, 0.f) * vw.x;
        acc += fmaxf(va.y + vb.y + vbi.y, 0.f) * vw.y;
        acc += fmaxf(va.z + vb.z + vbi.z, 0.f) * vw.z;
        acc += fmaxf(va.w + vb.w + vbi.w, 0.f) * vw.w;
    }
#pragma unroll
    for (int o = 16; o; o >>= 1) acc += __shfl_xor_sync(0xffffffffu, acc, o);
    if (lane == 0) {
        float z = acc + bm2[0];
        out[ei] = 1.0f / (1.0f + expf(-z));
    }
}

// ---------------- launch ----------------
extern "C" void kernel_launch(void* const* d_in, const int* in_sizes, int n_in,
                              void* d_out, int out_size) {
    const float* x    = (const float*)d_in[0];
    const int*   ei   = (const int*)d_in[1];     // edge_index delivered as int32
    const float* W1   = (const float*)d_in[2];
    const float* b1   = (const float*)d_in[3];
    const float* gamma= (const float*)d_in[4];
    const float* beta = (const float*)d_in[5];
    const float* W2   = (const float*)d_in[6];
    const float* b2   = (const float*)d_in[7];
    const float* Wm1  = (const float*)d_in[8];
    const float* bm1  = (const float*)d_in[9];
    const float* Wm2  = (const float*)d_in[10];
    const float* bm2  = (const float*)d_in[11];
    float* out = (float*)d_out;

    const int n = in_sizes[0] / 128;      // 50000
    const int e = in_sizes[1] / 2;        // 400000
    const int* src = ei;
    const int* dst = ei + e;

    // 1. degrees / norm
    k_init<<<(n + 255) / 256, 256>>>(n);
    k_deg_edges<<<(e + 255) / 256, 256>>>(dst, e);
    k_dinv<<<(n + 255) / 256, 256>>>(n);

    dim3 g1(256 / 64, (n + 127) / 128);   // 4 x 391

    // 2. gcn1: buf1 = x@W1 ; agg -> buf2
    k_sgemm<<<g1, 256>>>(x, 0, W1, 1, 0, n, 128, HD, HD);
    k_init_agg<<<(n * 64 + 255) / 256, 256>>>(b1, 0, n);
    k_edge_agg<<<(e * 64 + 255) / 256, 256>>>(src, dst, 0, e);

    // 3. batchnorm + relu: buf2 -> buf1
    k_bn_stats<<<512, 256>>>(n);
    k_bn_finalize<<<1, 256>>>(gamma, beta, n);
    k_bn_apply<<<(n * 64 + 255) / 256, 256>>>(n);

    // 4. gcn2: buf2 = buf1@W2 ; agg -> buf1 ; relu(buf1)
    k_sgemm<<<g1, 256>>>(nullptr, 1, W2, 2, 0, n, HD, HD, HD);
    k_init_agg<<<(n * 64 + 255) / 256, 256>>>(b2, 1, n);
    k_edge_agg<<<(e * 64 + 255) / 256, 256>>>(src, dst, 1, e);
    k_relu_buf1<<<(int)(((size_t)n * 64 + 255) / 256), 256>>>((size_t)n * 64);

    // 5. hoisted MLP layer 1: AB[:,0:256] = h2@Wm1_top, AB[:,256:512] = h2@Wm1_bot
    k_sgemm<<<g1, 256>>>(nullptr, 1, Wm1,            3, 0,  n, HD, HD, 512);
    k_sgemm<<<g1, 256>>>(nullptr, 1, Wm1 + 256 * HD, 3, HD, n, HD, HD, 512);

    // 6. per-edge epilogue
    k_edge_mlp<<<(e + 7) / 8, 256>>>(src, dst, bm1, Wm2, bm2, out, e);
}